// round 1
// baseline (speedup 1.0000x reference)
#include <cuda_runtime.h>
#include <cuda_bf16.h>
#include <math.h>

// ---------------- problem constants ----------------
#define B_    4
#define L_    3136
#define DM_   192       // d_model
#define DIN_  384       // d_in
#define NS_   16        // n_state
#define KDIR_ 4
#define RED_  48
#define NCH_  16        // scan chunks
#define LCH_  196       // L_/NCH_
#define NR_   44        // dt_rank + 2*n_state

// ---------------- scratch (static device globals; no allocation) ----------------
__device__ float g_mask[B_ * L_];
__device__ float g_xz[(size_t)B_ * L_ * 2 * DIN_];          // (b,l,768)
__device__ float g_u[(size_t)KDIR_ * B_ * L_ * DIN_];       // (z,p,384) scan order
__device__ float g_xdbl[(size_t)KDIR_ * B_ * L_ * NR_];     // (z,p,44)
__device__ float g_delta[(size_t)KDIR_ * B_ * L_ * DIN_];   // (z,p,384)
__device__ float g_Q[(size_t)KDIR_ * B_ * NCH_ * DIN_ * NS_];
__device__ float g_S[(size_t)KDIR_ * B_ * NCH_ * DIN_];
__device__ float g_Hs[(size_t)KDIR_ * B_ * NCH_ * DIN_ * NS_];
__device__ float g_y[(size_t)KDIR_ * B_ * L_ * DIN_];       // (z,l,384) original order
__device__ float g_gsum[KDIR_ * B_ * DIN_];
__device__ float g_catt[KDIR_ * B_ * DIN_];

// ---------------- direction permutation: scan position p -> original l ----------------
__device__ __forceinline__ int perm_idx(int k, int p) {
    int q = (k & 1) ? (L_ - 1 - p) : p;      // dirs 1,3 are flips
    if (k < 2) return q;                      // 'h' / 'h_flip'
    int wi = q % 7;
    int t  = q / 7;
    int hi = t % 7;
    int blk = t / 7;                          // hg*8 + wg
    int wg = blk & 7, hg = blk >> 3;
    return (hg * 7 + hi) * 56 + wg * 7 + wi;  // 'w7' / 'w7_flip'
}

// e[n] = r^(n+1), n = 0..15 (tree of multiplies, no serial chain)
__device__ __forceinline__ void pow_e(float r, float* e) {
    float r2 = r * r, r4 = r2 * r2, r8 = r4 * r4;
    e[0] = r;        e[1] = r2;       e[2] = r2 * r;    e[3] = r4;
    e[4] = r4 * r;   e[5] = r4 * r2;  e[6] = r4 * e[2]; e[7] = r8;
    e[8] = r8 * r;   e[9] = r8 * r2;  e[10] = r8 * e[2]; e[11] = r8 * r4;
    e[12] = r8 * e[4]; e[13] = r8 * e[5]; e[14] = r8 * e[6]; e[15] = r8 * r8;
}

// ---------------- mask: (x @ mask_w.T + mask_b) > 0 -> 1/0 ----------------
__global__ void k_mask(const float* __restrict__ X, const float* __restrict__ MW,
                       const float* __restrict__ MB) {
    int row = blockIdx.x * 8 + threadIdx.y;
    if (row >= B_ * L_) return;
    int lane = threadIdx.x;
    const float* xr = X + (size_t)row * DM_;
    float s = 0.f;
    for (int i = lane; i < DM_; i += 32) s += xr[i] * MW[i];
    #pragma unroll
    for (int o = 16; o; o >>= 1) s += __shfl_xor_sync(0xFFFFFFFFu, s, o);
    if (lane == 0) g_mask[row] = (s + MB[0] > 0.f) ? 1.f : 0.f;
}

// ---------------- xz = x @ in_proj_w.T : M=12544, N=768, K=192 ----------------
__global__ void k_xz(const float* __restrict__ X, const float* __restrict__ W) {
    __shared__ float As[32][68];
    __shared__ float Ws[32][68];
    int m0 = blockIdx.y * 64, n0 = blockIdx.x * 64;
    int tid = threadIdx.x;
    int tx = tid & 15, ty = tid >> 4;
    float acc[4][4] = {};
    for (int k0 = 0; k0 < 192; k0 += 32) {
        __syncthreads();
        #pragma unroll
        for (int i = 0; i < 8; i++) {
            int idx = tid + i * 256;
            int r = idx >> 5, kk = idx & 31;
            As[kk][r] = X[(size_t)(m0 + r) * 192 + k0 + kk];
            Ws[kk][r] = W[(size_t)(n0 + r) * 192 + k0 + kk];
        }
        __syncthreads();
        #pragma unroll
        for (int kk = 0; kk < 32; kk++) {
            float a[4], bv[4];
            #pragma unroll
            for (int i = 0; i < 4; i++) a[i] = As[kk][ty * 4 + i];
            #pragma unroll
            for (int j = 0; j < 4; j++) bv[j] = Ws[kk][tx * 4 + j];
            #pragma unroll
            for (int i = 0; i < 4; i++)
                #pragma unroll
                for (int j = 0; j < 4; j++) acc[i][j] += a[i] * bv[j];
        }
    }
    #pragma unroll
    for (int i = 0; i < 4; i++)
        #pragma unroll
        for (int j = 0; j < 4; j++)
            g_xz[(size_t)(m0 + ty * 4 + i) * 768 + n0 + tx * 4 + j] = acc[i][j];
}

// ---------------- depthwise causal conv + silu + mask -> u ----------------
__global__ void k_conv(const float* __restrict__ CW, const float* __restrict__ CB) {
    int z = blockIdx.z;              // z = k*B_ + b
    int k = z / B_, b = z % B_;
    int tx = threadIdx.x;
    int d = blockIdx.y * 128 + tx;
    int p0 = blockIdx.x * 32;
    __shared__ float xs[35][128];
    __shared__ float ms[32];
    for (int i = 0; i < 35; i++) {
        int p = p0 - 3 + i;
        float v = 0.f;
        if (p >= 0) {
            int l = perm_idx(k, p);
            v = g_xz[((size_t)b * L_ + l) * (2 * DIN_) + d] * g_mask[b * L_ + l];
        }
        xs[i][tx] = v;
    }
    if (tx < 32) {
        int l = perm_idx(k, p0 + tx);
        ms[tx] = g_mask[b * L_ + l];
    }
    __syncthreads();
    float w0 = CW[d * 4 + 0], w1 = CW[d * 4 + 1], w2 = CW[d * 4 + 2], w3 = CW[d * 4 + 3];
    float cb = CB[d];
    float* ob = g_u + ((size_t)z * L_ + p0) * DIN_ + d;
    #pragma unroll 4
    for (int j = 0; j < 32; j++) {
        float s = w0 * xs[j][tx] + w1 * xs[j + 1][tx] + w2 * xs[j + 2][tx] + w3 * xs[j + 3][tx] + cb;
        float sil = s / (1.f + __expf(-s));
        ob[(size_t)j * DIN_] = sil * ms[j];
    }
}

// ---------------- x_dbl[p][r] = sum_d u[p][d] * x_proj_w[k][r][d] ----------------
__global__ void k_xdbl(const float* __restrict__ XPW) {
    int z = blockIdx.y;
    int k = z / B_;
    int p0 = blockIdx.x * 64;
    __shared__ float Us[32][68];
    __shared__ float Ws[32][NR_];
    int tid = threadIdx.x;
    int pl = tid >> 2, rq = tid & 3;
    float acc[11] = {};
    const float* ub = g_u + (size_t)z * L_ * DIN_;
    for (int k0 = 0; k0 < DIN_; k0 += 32) {
        __syncthreads();
        #pragma unroll
        for (int i = 0; i < 8; i++) {
            int idx = tid + i * 256;
            int r = idx >> 5, kk = idx & 31;
            Us[kk][r] = ub[(size_t)(p0 + r) * DIN_ + k0 + kk];
        }
        #pragma unroll
        for (int i = 0; i < 6; i++) {
            int idx = tid + i * 256;
            if (idx < NR_ * 32) {
                int r = idx >> 5, kk = idx & 31;
                Ws[kk][r] = XPW[((size_t)k * NR_ + r) * DIN_ + k0 + kk];
            }
        }
        __syncthreads();
        #pragma unroll
        for (int kk = 0; kk < 32; kk++) {
            float a = Us[kk][pl];
            #pragma unroll
            for (int j = 0; j < 11; j++) acc[j] += a * Ws[kk][rq + 4 * j];
        }
    }
    float* ob = g_xdbl + ((size_t)z * L_ + p0) * NR_;
    #pragma unroll
    for (int j = 0; j < 11; j++) ob[(size_t)pl * NR_ + rq + 4 * j] = acc[j];
}

// ---------------- delta = softplus(dt_w @ x_dbl[:12] + dt_b) ----------------
__global__ void k_delta(const float* __restrict__ DTW, const float* __restrict__ DTB) {
    int z = blockIdx.y;
    int k = z / B_;
    int p0 = blockIdx.x * 16;
    __shared__ float xd[16][12];
    int tid = threadIdx.x;
    if (tid < 192) {
        int pl = tid / 12, r = tid % 12;
        xd[pl][r] = g_xdbl[((size_t)z * L_ + p0 + pl) * NR_ + r];
    }
    __syncthreads();
    int d = tid;
    float wt[12];
    #pragma unroll
    for (int r = 0; r < 12; r++) wt[r] = DTW[((size_t)k * DIN_ + d) * 12 + r];
    float bias = DTB[k * DIN_ + d];
    float* ob = g_delta + ((size_t)z * L_ + p0) * DIN_ + d;
    for (int pl = 0; pl < 16; pl++) {
        float s = bias;
        #pragma unroll
        for (int r = 0; r < 12; r++) s += xd[pl][r] * wt[r];
        float sp = (s > 20.f) ? s : log1pf(__expf(s));
        ob[(size_t)pl * DIN_] = sp;
    }
}

__global__ void k_zero() {
    int i = blockIdx.x * 256 + threadIdx.x;
    if (i < KDIR_ * B_ * DIN_) g_gsum[i] = 0.f;
}

// ---------------- scan pass 1: per-chunk local scan, summaries (Q, sum delta) ----------------
__global__ void k_scan1(const float* __restrict__ A_log) {
    int z = blockIdx.z;
    int d = blockIdx.y * 128 + threadIdx.x;
    int c = blockIdx.x;
    float a2[NS_];
    bool pok = true;
    #pragma unroll
    for (int n = 0; n < NS_; n++) {
        float an = -__expf(A_log[d * NS_ + n]);
        a2[n] = an * 1.4426950408889634f;
        if (fabsf(an + (float)(n + 1)) > 1e-4f * (float)(n + 1)) pok = false;
    }
    const float* dl = g_delta + ((size_t)z * L_ + c * LCH_) * DIN_ + d;
    const float* ul = g_u + ((size_t)z * L_ + c * LCH_) * DIN_ + d;
    float h[NS_];
    #pragma unroll
    for (int n = 0; n < NS_; n++) h[n] = 0.f;
    float sdel = 0.f;
    for (int s = 0; s < LCH_; s++) {
        float de = dl[(size_t)s * DIN_];
        float uu = ul[(size_t)s * DIN_];
        float du = de * uu;
        float e[NS_];
        if (pok) {
            pow_e(__expf(-de), e);
        } else {
            #pragma unroll
            for (int n = 0; n < NS_; n++) e[n] = exp2f(de * a2[n]);
        }
        int p = c * LCH_ + s;
        const float4* bp = (const float4*)(g_xdbl + ((size_t)z * L_ + p) * NR_ + 12);
        float4 b0 = bp[0], b1 = bp[1], b2 = bp[2], b3 = bp[3];
        float bb[NS_] = {b0.x, b0.y, b0.z, b0.w, b1.x, b1.y, b1.z, b1.w,
                         b2.x, b2.y, b2.z, b2.w, b3.x, b3.y, b3.z, b3.w};
        #pragma unroll
        for (int n = 0; n < NS_; n++) h[n] = e[n] * h[n] + du * bb[n];
        sdel += de;
    }
    float* q = g_Q + (((size_t)z * NCH_ + c) * DIN_ + d) * NS_;
    #pragma unroll
    for (int n = 0; n < NS_; n++) q[n] = h[n];
    g_S[((size_t)z * NCH_ + c) * DIN_ + d] = sdel;
}

// ---------------- scan fix: prefix over chunks -> h_start per chunk ----------------
__global__ void k_fix(const float* __restrict__ A_log) {
    int z = blockIdx.x;
    int d = threadIdx.x;
    float a2[NS_];
    #pragma unroll
    for (int n = 0; n < NS_; n++) a2[n] = -__expf(A_log[d * NS_ + n]) * 1.4426950408889634f;
    float hs[NS_];
    #pragma unroll
    for (int n = 0; n < NS_; n++) hs[n] = 0.f;
    for (int c = 0; c < NCH_; c++) {
        float* H = g_Hs + (((size_t)z * NCH_ + c) * DIN_ + d) * NS_;
        #pragma unroll
        for (int n = 0; n < NS_; n++) H[n] = hs[n];
        float sd = g_S[((size_t)z * NCH_ + c) * DIN_ + d];
        const float* Q = g_Q + (((size_t)z * NCH_ + c) * DIN_ + d) * NS_;
        #pragma unroll
        for (int n = 0; n < NS_; n++) hs[n] = exp2f(a2[n] * sd) * hs[n] + Q[n];
    }
}

// ---------------- scan pass 2: replay with h_start, emit y*silu(z), scatter ----------------
__global__ void k_scan2(const float* __restrict__ A_log, const float* __restrict__ Dsk) {
    int z = blockIdx.z;
    int k = z / B_, b = z % B_;
    int d = blockIdx.y * 128 + threadIdx.x;
    int c = blockIdx.x;
    float a2[NS_];
    bool pok = true;
    #pragma unroll
    for (int n = 0; n < NS_; n++) {
        float an = -__expf(A_log[d * NS_ + n]);
        a2[n] = an * 1.4426950408889634f;
        if (fabsf(an + (float)(n + 1)) > 1e-4f * (float)(n + 1)) pok = false;
    }
    const float* dl = g_delta + ((size_t)z * L_ + c * LCH_) * DIN_ + d;
    const float* ul = g_u + ((size_t)z * L_ + c * LCH_) * DIN_ + d;
    const float* H = g_Hs + (((size_t)z * NCH_ + c) * DIN_ + d) * NS_;
    float h[NS_];
    #pragma unroll
    for (int n = 0; n < NS_; n++) h[n] = H[n];
    float dsk = Dsk[d];
    for (int s = 0; s < LCH_; s++) {
        float de = dl[(size_t)s * DIN_];
        float uu = ul[(size_t)s * DIN_];
        float du = de * uu;
        float e[NS_];
        if (pok) {
            pow_e(__expf(-de), e);
        } else {
            #pragma unroll
            for (int n = 0; n < NS_; n++) e[n] = exp2f(de * a2[n]);
        }
        int p = c * LCH_ + s;
        const float* row = g_xdbl + ((size_t)z * L_ + p) * NR_;
        const float4* bp = (const float4*)(row + 12);
        const float4* cp = (const float4*)(row + 28);
        float4 b0 = bp[0], b1 = bp[1], b2 = bp[2], b3 = bp[3];
        float4 c0 = cp[0], c1 = cp[1], c2 = cp[2], c3 = cp[3];
        float bb[NS_] = {b0.x, b0.y, b0.z, b0.w, b1.x, b1.y, b1.z, b1.w,
                         b2.x, b2.y, b2.z, b2.w, b3.x, b3.y, b3.z, b3.w};
        float cc[NS_] = {c0.x, c0.y, c0.z, c0.w, c1.x, c1.y, c1.z, c1.w,
                         c2.x, c2.y, c2.z, c2.w, c3.x, c3.y, c3.z, c3.w};
        float y = 0.f;
        #pragma unroll
        for (int n = 0; n < NS_; n++) {
            h[n] = e[n] * h[n] + du * bb[n];
            y += h[n] * cc[n];
        }
        y += dsk * uu;
        int l = perm_idx(k, p);
        float zv = g_xz[((size_t)b * L_ + l) * (2 * DIN_) + DIN_ + d];
        y *= zv / (1.f + __expf(-zv));
        g_y[((size_t)z * L_ + l) * DIN_ + d] = y;
    }
}

// ---------------- LayerNorm over d, accumulate per-(z,d) mean of xn ----------------
__global__ void k_lnstats(const float* __restrict__ G, const float* __restrict__ Bt) {
    int k = blockIdx.z, b = blockIdx.y;
    int z = k * B_ + b;
    int d = threadIdx.x;
    int lane = d & 31, wid = d >> 5;
    __shared__ float s1[12], s2[12];
    float g = G[d], bt = Bt[d];
    float local = 0.f;
    for (int r = 0; r < 8; r++) {
        int l = blockIdx.x * 8 + r;
        float v = g_y[((size_t)z * L_ + l) * DIN_ + d];
        float a = v, c2 = v * v;
        #pragma unroll
        for (int o = 16; o; o >>= 1) {
            a += __shfl_xor_sync(0xFFFFFFFFu, a, o);
            c2 += __shfl_xor_sync(0xFFFFFFFFu, c2, o);
        }
        if (lane == 0) { s1[wid] = a; s2[wid] = c2; }
        __syncthreads();
        if (d == 0) {
            float aa = 0.f, cc = 0.f;
            for (int i = 0; i < 12; i++) { aa += s1[i]; cc += s2[i]; }
            s1[0] = aa; s2[0] = cc;
        }
        __syncthreads();
        float mu = s1[0] * (1.f / DIN_);
        float var = s2[0] * (1.f / DIN_) - mu * mu;
        float rstd = rsqrtf(var + 1e-5f);
        local += (v - mu) * rstd * g + bt;
        __syncthreads();
    }
    atomicAdd(&g_gsum[z * DIN_ + d], local);
}

// ---------------- channel attention: gelu(g@red.T) -> sigmoid(.@sel.T) ----------------
__global__ void k_attn(const float* __restrict__ RW, const float* __restrict__ RB,
                       const float* __restrict__ SW, const float* __restrict__ SB) {
    int z = blockIdx.x;
    __shared__ float gg[DIN_];
    __shared__ float tt[RED_];
    int d = threadIdx.x;
    int lane = d & 31, wid = d >> 5;
    gg[d] = g_gsum[z * DIN_ + d] * (1.f / (float)L_);
    __syncthreads();
    #pragma unroll
    for (int jj = 0; jj < 4; jj++) {
        int j = wid * 4 + jj;
        float s = 0.f;
        for (int i = lane; i < DIN_; i += 32) s += gg[i] * RW[(size_t)j * DIN_ + i];
        #pragma unroll
        for (int o = 16; o; o >>= 1) s += __shfl_xor_sync(0xFFFFFFFFu, s, o);
        if (lane == 0) {
            float v = s + RB[j];
            tt[j] = 0.5f * v * (1.f + erff(v * 0.70710678118f));
        }
    }
    __syncthreads();
    float s = SB[d];
    #pragma unroll
    for (int j = 0; j < RED_; j++) s += tt[j] * SW[(size_t)d * RED_ + j];
    g_catt[z * DIN_ + d] = 1.f / (1.f + __expf(-s));
}

// ---------------- out = (sum_k y_k * catt_k) @ out_proj.T + bias ----------------
__global__ void k_out(const float* __restrict__ W, const float* __restrict__ BI,
                      float* __restrict__ OUT) {
    __shared__ float As[32][68];
    __shared__ float Ws[32][68];
    __shared__ float Cs[KDIR_][32];
    int m0 = blockIdx.y * 64, n0 = blockIdx.x * 64;
    int b = m0 / L_;
    int l0 = m0 - b * L_;
    int tid = threadIdx.x;
    int tx = tid & 15, ty = tid >> 4;
    float acc[4][4] = {};
    for (int k0 = 0; k0 < DIN_; k0 += 32) {
        __syncthreads();
        if (tid < 128) {
            int dir = tid >> 5, kk = tid & 31;
            Cs[dir][kk] = g_catt[(dir * B_ + b) * DIN_ + k0 + kk];
        }
        __syncthreads();
        #pragma unroll
        for (int i = 0; i < 8; i++) {
            int idx = tid + i * 256;
            int r = idx >> 5, kk = idx & 31;
            float s = 0.f;
            #pragma unroll
            for (int dir = 0; dir < KDIR_; dir++)
                s += g_y[((size_t)(dir * B_ + b) * L_ + l0 + r) * DIN_ + k0 + kk] * Cs[dir][kk];
            As[kk][r] = s;
            Ws[kk][r] = W[(size_t)(n0 + r) * DIN_ + k0 + kk];
        }
        __syncthreads();
        #pragma unroll
        for (int kk = 0; kk < 32; kk++) {
            float a[4], bv[4];
            #pragma unroll
            for (int i = 0; i < 4; i++) a[i] = As[kk][ty * 4 + i];
            #pragma unroll
            for (int j = 0; j < 4; j++) bv[j] = Ws[kk][tx * 4 + j];
            #pragma unroll
            for (int i = 0; i < 4; i++)
                #pragma unroll
                for (int j = 0; j < 4; j++) acc[i][j] += a[i] * bv[j];
        }
    }
    #pragma unroll
    for (int i = 0; i < 4; i++)
        #pragma unroll
        for (int j = 0; j < 4; j++)
            OUT[(size_t)(m0 + ty * 4 + i) * DM_ + n0 + tx * 4 + j] = acc[i][j] + BI[n0 + tx * 4 + j];
}

// ---------------- launch ----------------
extern "C" void kernel_launch(void* const* d_in, const int* in_sizes, int n_in,
                              void* d_out, int out_size) {
    const float* x          = (const float*)d_in[0];
    const float* in_proj_w  = (const float*)d_in[1];
    const float* conv_w     = (const float*)d_in[2];
    const float* conv_b     = (const float*)d_in[3];
    const float* x_proj_w   = (const float*)d_in[4];
    const float* dt_w       = (const float*)d_in[5];
    const float* dt_b       = (const float*)d_in[6];
    const float* A_log      = (const float*)d_in[7];
    const float* D_skip     = (const float*)d_in[8];
    const float* out_proj_w = (const float*)d_in[9];
    const float* out_proj_b = (const float*)d_in[10];
    const float* ln_g       = (const float*)d_in[11];
    const float* ln_b       = (const float*)d_in[12];
    const float* red_w      = (const float*)d_in[13];
    const float* red_b      = (const float*)d_in[14];
    const float* sel_w      = (const float*)d_in[15];
    const float* sel_b      = (const float*)d_in[16];
    const float* mask_w     = (const float*)d_in[17];
    const float* mask_b     = (const float*)d_in[18];
    float* out = (float*)d_out;

    k_mask<<<dim3((B_ * L_ + 7) / 8), dim3(32, 8)>>>(x, mask_w, mask_b);
    k_xz<<<dim3(12, 196), 256>>>(x, in_proj_w);
    k_conv<<<dim3(L_ / 32, 3, KDIR_ * B_), 128>>>(conv_w, conv_b);
    k_xdbl<<<dim3(L_ / 64, KDIR_ * B_), 256>>>(x_proj_w);
    k_delta<<<dim3(L_ / 16, KDIR_ * B_), 384>>>(dt_w, dt_b);
    k_zero<<<24, 256>>>();
    k_scan1<<<dim3(NCH_, 3, KDIR_ * B_), 128>>>(A_log);
    k_fix<<<KDIR_ * B_, DIN_>>>(A_log);
    k_scan2<<<dim3(NCH_, 3, KDIR_ * B_), 128>>>(A_log, D_skip);
    k_lnstats<<<dim3(L_ / 8, B_, KDIR_), DIN_>>>(ln_g, ln_b);
    k_attn<<<KDIR_ * B_, DIN_>>>(red_w, red_b, sel_w, sel_b);
    k_out<<<dim3(3, 196), 256>>>(out_proj_w, out_proj_b, out);
}

// round 3
// speedup vs baseline: 1.1887x; 1.1887x over previous
#include <cuda_runtime.h>
#include <cuda_bf16.h>
#include <math.h>

// ---------------- problem constants ----------------
#define B_    4
#define L_    3136
#define DM_   192       // d_model
#define DIN_  384       // d_in
#define NS_   16        // n_state
#define KDIR_ 4
#define RED_  48
#define NCH_  16        // scan chunks
#define LCH_  196       // L_/NCH_
#define NR_   44        // dt_rank + 2*n_state
#define LOG2E 1.4426950408889634f

// ---------------- scratch (static device globals; no allocation) ----------------
__device__ float g_mask[B_ * L_];
__device__ float g_xz[(size_t)B_ * L_ * 2 * DIN_];                 // (b,l,768)
__device__ float g_u[((size_t)KDIR_ * B_ * L_ + 128) * DIN_];      // (z,p,384) + pad tile
__device__ float g_xdbl[(size_t)KDIR_ * B_ * L_ * NR_];            // (z,p,44)
__device__ float g_Q[(size_t)KDIR_ * B_ * NCH_ * DIN_ * NS_];
__device__ float g_S[(size_t)KDIR_ * B_ * NCH_ * DIN_];
__device__ float g_Hs[(size_t)KDIR_ * B_ * NCH_ * DIN_ * NS_];
__device__ float g_y[(size_t)KDIR_ * B_ * L_ * DIN_];              // (z,l,384) original order
__device__ float g_gsum[KDIR_ * B_ * DIN_];
__device__ float g_catt[KDIR_ * B_ * DIN_];

// ---------------- direction permutation: scan position p -> original l ----------------
__device__ __forceinline__ int perm_idx(int k, int p) {
    int q = (k & 1) ? (L_ - 1 - p) : p;      // dirs 1,3 are flips
    if (k < 2) return q;                      // 'h' / 'h_flip'
    int wi = q % 7;
    int t  = q / 7;
    int hi = t % 7;
    int blk = t / 7;                          // hg*8 + wg
    int wg = blk & 7, hg = blk >> 3;
    return (hg * 7 + hi) * 56 + wg * 7 + wi;  // 'w7' / 'w7_flip'
}

// e[n] = r^(n+1), n = 0..15 (tree of multiplies, no serial chain)
__device__ __forceinline__ void pow_e(float r, float* e) {
    float r2 = r * r, r4 = r2 * r2, r8 = r4 * r4;
    e[0] = r;        e[1] = r2;       e[2] = r2 * r;    e[3] = r4;
    e[4] = r4 * r;   e[5] = r4 * r2;  e[6] = r4 * e[2]; e[7] = r8;
    e[8] = r8 * r;   e[9] = r8 * r2;  e[10] = r8 * e[2]; e[11] = r8 * r4;
    e[12] = r8 * e[4]; e[13] = r8 * e[5]; e[14] = r8 * e[6]; e[15] = r8 * r8;
}

// rare exact-fallback path (A not the structured -(n+1) pattern)
__device__ __noinline__ void exp_general(float de, const float* __restrict__ A_log,
                                         int d, float* e) {
    #pragma unroll
    for (int n = 0; n < NS_; n++)
        e[n] = exp2f(de * (-__expf(A_log[d * NS_ + n])) * LOG2E);
}

__device__ __forceinline__ float softplusf(float s) {
    return (s > 20.f) ? s : log1pf(__expf(s));
}

// ---------------- mask: (x @ mask_w.T + mask_b) > 0 -> 1/0 ----------------
__global__ void k_mask(const float* __restrict__ X, const float* __restrict__ MW,
                       const float* __restrict__ MB) {
    int row = blockIdx.x * 8 + threadIdx.y;
    if (row >= B_ * L_) return;
    int lane = threadIdx.x;
    const float* xr = X + (size_t)row * DM_;
    float s = 0.f;
    for (int i = lane; i < DM_; i += 32) s += xr[i] * MW[i];
    #pragma unroll
    for (int o = 16; o; o >>= 1) s += __shfl_xor_sync(0xFFFFFFFFu, s, o);
    if (lane == 0) g_mask[row] = (s + MB[0] > 0.f) ? 1.f : 0.f;
}

// ---------------- xz = x @ in_proj_w.T : M=12544, N=768, K=192 ----------------
// tile 128M x 64N, float4-over-K shared
__global__ __launch_bounds__(256) void k_xz(const float* __restrict__ X,
                                            const float* __restrict__ W) {
    __shared__ float4 As[128][9];
    __shared__ float4 Ws[64][9];
    int m0 = blockIdx.y * 128, n0 = blockIdx.x * 64;
    int tid = threadIdx.x;
    int tx = tid & 15, ty = tid >> 4;
    const float4* X4 = (const float4*)X;
    const float4* W4 = (const float4*)W;
    float acc[8][4] = {};
    for (int k0 = 0; k0 < 48; k0 += 8) {
        __syncthreads();
        #pragma unroll
        for (int i = 0; i < 4; i++) {
            int idx = tid + i * 256;
            int r = idx >> 3, kq = idx & 7;
            As[r][kq] = X4[(size_t)(m0 + r) * 48 + k0 + kq];
        }
        #pragma unroll
        for (int i = 0; i < 2; i++) {
            int idx = tid + i * 256;
            int r = idx >> 3, kq = idx & 7;
            Ws[r][kq] = W4[(size_t)(n0 + r) * 48 + k0 + kq];
        }
        __syncthreads();
        #pragma unroll
        for (int kq = 0; kq < 8; kq++) {
            float4 a4[8], w4[4];
            #pragma unroll
            for (int i = 0; i < 8; i++) a4[i] = As[ty * 8 + i][kq];
            #pragma unroll
            for (int j = 0; j < 4; j++) w4[j] = Ws[tx + 16 * j][kq];
            #pragma unroll
            for (int i = 0; i < 8; i++)
                #pragma unroll
                for (int j = 0; j < 4; j++)
                    acc[i][j] += a4[i].x * w4[j].x + a4[i].y * w4[j].y +
                                 a4[i].z * w4[j].z + a4[i].w * w4[j].w;
        }
    }
    #pragma unroll
    for (int i = 0; i < 8; i++)
        #pragma unroll
        for (int j = 0; j < 4; j++)
            g_xz[(size_t)(m0 + ty * 8 + i) * 768 + n0 + tx + 16 * j] = acc[i][j];
}

// ---------------- depthwise causal conv + silu + mask -> u ----------------
__global__ void k_conv(const float* __restrict__ CW, const float* __restrict__ CB) {
    int z = blockIdx.z;              // z = k*B_ + b
    int k = z / B_, b = z % B_;
    int tx = threadIdx.x;
    int d = blockIdx.y * 128 + tx;
    int p0 = blockIdx.x * 32;
    __shared__ float xs[35][128];
    __shared__ float ms[32];
    for (int i = 0; i < 35; i++) {
        int p = p0 - 3 + i;
        float v = 0.f;
        if (p >= 0) {
            int l = perm_idx(k, p);
            v = g_xz[((size_t)b * L_ + l) * (2 * DIN_) + d] * g_mask[b * L_ + l];
        }
        xs[i][tx] = v;
    }
    if (tx < 32) {
        int l = perm_idx(k, p0 + tx);
        ms[tx] = g_mask[b * L_ + l];
    }
    __syncthreads();
    float w0 = CW[d * 4 + 0], w1 = CW[d * 4 + 1], w2 = CW[d * 4 + 2], w3 = CW[d * 4 + 3];
    float cb = CB[d];
    float* ob = g_u + ((size_t)z * L_ + p0) * DIN_ + d;
    #pragma unroll 4
    for (int j = 0; j < 32; j++) {
        float s = w0 * xs[j][tx] + w1 * xs[j + 1][tx] + w2 * xs[j + 2][tx] + w3 * xs[j + 3][tx] + cb;
        float sil = s / (1.f + __expf(-s));
        ob[(size_t)j * DIN_] = sil * ms[j];
    }
}

// ---------------- x_dbl[p][r] = sum_d u[p][d] * x_proj_w[k][r][d] ----------------
// batched GEMM: per z, M=L (tiles of 128 pos), N=44, K=384
__global__ __launch_bounds__(128) void k_xdbl(const float* __restrict__ XPW) {
    __shared__ float4 Us[128][9];
    __shared__ float4 Ws[NR_][9];
    int z = blockIdx.y;
    int k = z >> 2;
    int p0 = blockIdx.x * 128;
    int tid = threadIdx.x;
    int rq = tid & 3, pg = tid >> 2;   // pg 0..31
    const float4* U4 = (const float4*)g_u;
    const float4* W4 = (const float4*)XPW;
    float acc[4][11] = {};
    for (int k0 = 0; k0 < 96; k0 += 8) {
        __syncthreads();
        #pragma unroll
        for (int i = 0; i < 8; i++) {
            int idx = tid + i * 128;
            int r = idx >> 3, kq = idx & 7;
            Us[r][kq] = U4[((size_t)z * L_ + p0 + r) * 96 + k0 + kq];
        }
        #pragma unroll
        for (int i = 0; i < 3; i++) {
            int idx = tid + i * 128;
            if (idx < NR_ * 8) {
                int r = idx >> 3, kq = idx & 7;
                Ws[r][kq] = W4[((size_t)k * NR_ + r) * 96 + k0 + kq];
            }
        }
        __syncthreads();
        #pragma unroll
        for (int kq = 0; kq < 8; kq++) {
            float4 u4[4], w4[11];
            #pragma unroll
            for (int i = 0; i < 4; i++) u4[i] = Us[pg * 4 + i][kq];
            #pragma unroll
            for (int j = 0; j < 11; j++) w4[j] = Ws[rq + 4 * j][kq];
            #pragma unroll
            for (int i = 0; i < 4; i++)
                #pragma unroll
                for (int j = 0; j < 11; j++)
                    acc[i][j] += u4[i].x * w4[j].x + u4[i].y * w4[j].y +
                                 u4[i].z * w4[j].z + u4[i].w * w4[j].w;
        }
    }
    #pragma unroll
    for (int i = 0; i < 4; i++) {
        int p = p0 + pg * 4 + i;
        if (p < L_) {
            float* ob = g_xdbl + ((size_t)z * L_ + p) * NR_;
            #pragma unroll
            for (int j = 0; j < 11; j++) ob[rq + 4 * j] = acc[i][j];
        }
    }
}

__global__ void k_zero() {
    int i = blockIdx.x * 256 + threadIdx.x;
    if (i < KDIR_ * B_ * DIN_) g_gsum[i] = 0.f;
}

// ---------------- scan pass 1: per-chunk local scan (delta fused), summaries ----------------
__global__ __launch_bounds__(128) void k_scan1(const float* __restrict__ A_log,
                                               const float* __restrict__ DTW,
                                               const float* __restrict__ DTB) {
    int z = blockIdx.z;
    int k = z >> 2;
    int d = blockIdx.y * 128 + threadIdx.x;
    int c = blockIdx.x;
    float wt[12];
    #pragma unroll
    for (int r = 0; r < 12; r++) wt[r] = DTW[((size_t)k * DIN_ + d) * 12 + r];
    float bias = DTB[k * DIN_ + d];
    bool pok = true;
    #pragma unroll
    for (int n = 0; n < NS_; n++) {
        float an = -__expf(A_log[d * NS_ + n]);
        if (fabsf(an + (float)(n + 1)) > 1e-4f * (float)(n + 1)) pok = false;
    }
    const float* ul = g_u + ((size_t)z * L_ + c * LCH_) * DIN_ + d;
    const float* xr = g_xdbl + ((size_t)z * L_ + c * LCH_) * NR_;
    float h[NS_];
    #pragma unroll
    for (int n = 0; n < NS_; n++) h[n] = 0.f;
    float sdel = 0.f;
    for (int s = 0; s < LCH_; s++) {
        const float* row = xr + (size_t)s * NR_;
        const float4* dp = (const float4*)row;
        float4 x0 = dp[0], x1 = dp[1], x2 = dp[2];
        float sdt = bias;
        sdt += x0.x * wt[0] + x0.y * wt[1] + x0.z * wt[2] + x0.w * wt[3];
        sdt += x1.x * wt[4] + x1.y * wt[5] + x1.z * wt[6] + x1.w * wt[7];
        sdt += x2.x * wt[8] + x2.y * wt[9] + x2.z * wt[10] + x2.w * wt[11];
        float de = softplusf(sdt);
        float uu = ul[(size_t)s * DIN_];
        float du = de * uu;
        float e[NS_];
        if (pok) pow_e(__expf(-de), e);
        else     exp_general(de, A_log, d, e);
        const float4* bp = (const float4*)(row + 12);
        float4 b0 = bp[0], b1 = bp[1], b2 = bp[2], b3 = bp[3];
        float bb[NS_] = {b0.x, b0.y, b0.z, b0.w, b1.x, b1.y, b1.z, b1.w,
                         b2.x, b2.y, b2.z, b2.w, b3.x, b3.y, b3.z, b3.w};
        #pragma unroll
        for (int n = 0; n < NS_; n++) h[n] = e[n] * h[n] + du * bb[n];
        sdel += de;
    }
    float* q = g_Q + (((size_t)z * NCH_ + c) * DIN_ + d) * NS_;
    #pragma unroll
    for (int n = 0; n < NS_; n++) q[n] = h[n];
    g_S[((size_t)z * NCH_ + c) * DIN_ + d] = sdel;
}

// ---------------- scan fix: prefix over chunks -> h_start per chunk ----------------
__global__ void k_fix(const float* __restrict__ A_log) {
    int z = blockIdx.x;
    int d = threadIdx.x;
    float a2[NS_];
    #pragma unroll
    for (int n = 0; n < NS_; n++) a2[n] = -__expf(A_log[d * NS_ + n]) * LOG2E;
    float hs[NS_];
    #pragma unroll
    for (int n = 0; n < NS_; n++) hs[n] = 0.f;
    for (int c = 0; c < NCH_; c++) {
        float* H = g_Hs + (((size_t)z * NCH_ + c) * DIN_ + d) * NS_;
        #pragma unroll
        for (int n = 0; n < NS_; n++) H[n] = hs[n];
        float sd = g_S[((size_t)z * NCH_ + c) * DIN_ + d];
        const float* Q = g_Q + (((size_t)z * NCH_ + c) * DIN_ + d) * NS_;
        #pragma unroll
        for (int n = 0; n < NS_; n++) hs[n] = exp2f(a2[n] * sd) * hs[n] + Q[n];
    }
}

// ---------------- scan pass 2: replay with h_start, emit y*silu(z), scatter ----------------
__global__ __launch_bounds__(128) void k_scan2(const float* __restrict__ A_log,
                                               const float* __restrict__ DTW,
                                               const float* __restrict__ DTB,
                                               const float* __restrict__ Dsk) {
    int z = blockIdx.z;
    int k = z >> 2, b = z & 3;
    int d = blockIdx.y * 128 + threadIdx.x;
    int c = blockIdx.x;
    float wt[12];
    #pragma unroll
    for (int r = 0; r < 12; r++) wt[r] = DTW[((size_t)k * DIN_ + d) * 12 + r];
    float bias = DTB[k * DIN_ + d];
    bool pok = true;
    #pragma unroll
    for (int n = 0; n < NS_; n++) {
        float an = -__expf(A_log[d * NS_ + n]);
        if (fabsf(an + (float)(n + 1)) > 1e-4f * (float)(n + 1)) pok = false;
    }
    const float* ul = g_u + ((size_t)z * L_ + c * LCH_) * DIN_ + d;
    const float* xr = g_xdbl + ((size_t)z * L_ + c * LCH_) * NR_;
    const float* H = g_Hs + (((size_t)z * NCH_ + c) * DIN_ + d) * NS_;
    float h[NS_];
    #pragma unroll
    for (int n = 0; n < NS_; n++) h[n] = H[n];
    float dsk = Dsk[d];
    for (int s = 0; s < LCH_; s++) {
        const float* row = xr + (size_t)s * NR_;
        const float4* dp = (const float4*)row;
        float4 x0 = dp[0], x1 = dp[1], x2 = dp[2];
        float sdt = bias;
        sdt += x0.x * wt[0] + x0.y * wt[1] + x0.z * wt[2] + x0.w * wt[3];
        sdt += x1.x * wt[4] + x1.y * wt[5] + x1.z * wt[6] + x1.w * wt[7];
        sdt += x2.x * wt[8] + x2.y * wt[9] + x2.z * wt[10] + x2.w * wt[11];
        float de = softplusf(sdt);
        float uu = ul[(size_t)s * DIN_];
        float du = de * uu;
        float e[NS_];
        if (pok) pow_e(__expf(-de), e);
        else     exp_general(de, A_log, d, e);
        const float4* bp = (const float4*)(row + 12);
        const float4* cp = (const float4*)(row + 28);
        float4 b0 = bp[0], b1 = bp[1], b2 = bp[2], b3 = bp[3];
        float4 c0 = cp[0], c1 = cp[1], c2 = cp[2], c3 = cp[3];
        float bb[NS_] = {b0.x, b0.y, b0.z, b0.w, b1.x, b1.y, b1.z, b1.w,
                         b2.x, b2.y, b2.z, b2.w, b3.x, b3.y, b3.z, b3.w};
        float cc[NS_] = {c0.x, c0.y, c0.z, c0.w, c1.x, c1.y, c1.z, c1.w,
                         c2.x, c2.y, c2.z, c2.w, c3.x, c3.y, c3.z, c3.w};
        float y = 0.f;
        #pragma unroll
        for (int n = 0; n < NS_; n++) {
            h[n] = e[n] * h[n] + du * bb[n];
            y += h[n] * cc[n];
        }
        y += dsk * uu;
        int p = c * LCH_ + s;
        int l = perm_idx(k, p);
        float zv = g_xz[((size_t)b * L_ + l) * (2 * DIN_) + DIN_ + d];
        y *= zv / (1.f + __expf(-zv));
        g_y[((size_t)z * L_ + l) * DIN_ + d] = y;
    }
}

// ---------------- LayerNorm over d, warp-per-row, accumulate per-(z,d) sum of xn ----------------
__global__ __launch_bounds__(384) void k_lnstats(const float* __restrict__ G,
                                                 const float* __restrict__ Bt) {
    int kdir = blockIdx.z, b = blockIdx.y;
    int z = kdir * B_ + b;
    int tid = threadIdx.x;
    int w = tid >> 5, lane = tid & 31;
    int gw = blockIdx.x * 12 + w;     // 0..191 with grid.x = 16
    float gr[12], br[12], acc[12];
    #pragma unroll
    for (int j = 0; j < 12; j++) {
        int d = lane + 32 * j;
        gr[j] = G[d]; br[j] = Bt[d]; acc[j] = 0.f;
    }
    for (int l = gw; l < L_; l += 192) {
        const float* yr = g_y + ((size_t)z * L_ + l) * DIN_;
        float v[12];
        float s1 = 0.f, s2 = 0.f;
        #pragma unroll
        for (int j = 0; j < 12; j++) {
            v[j] = yr[lane + 32 * j];
            s1 += v[j];
            s2 += v[j] * v[j];
        }
        #pragma unroll
        for (int o = 16; o; o >>= 1) {
            s1 += __shfl_xor_sync(0xFFFFFFFFu, s1, o);
            s2 += __shfl_xor_sync(0xFFFFFFFFu, s2, o);
        }
        float mu = s1 * (1.f / DIN_);
        float var = s2 * (1.f / DIN_) - mu * mu;
        float rstd = rsqrtf(var + 1e-5f);
        #pragma unroll
        for (int j = 0; j < 12; j++)
            acc[j] += (v[j] - mu) * rstd * gr[j] + br[j];
    }
    #pragma unroll
    for (int j = 0; j < 12; j++)
        atomicAdd(&g_gsum[z * DIN_ + lane + 32 * j], acc[j]);
}

// ---------------- channel attention: gelu(g@red.T) -> sigmoid(.@sel.T) ----------------
__global__ void k_attn(const float* __restrict__ RW, const float* __restrict__ RB,
                       const float* __restrict__ SW, const float* __restrict__ SB) {
    int z = blockIdx.x;
    __shared__ float gg[DIN_];
    __shared__ float tt[RED_];
    int d = threadIdx.x;
    int lane = d & 31, wid = d >> 5;
    gg[d] = g_gsum[z * DIN_ + d] * (1.f / (float)L_);
    __syncthreads();
    #pragma unroll
    for (int jj = 0; jj < 4; jj++) {
        int j = wid * 4 + jj;
        float s = 0.f;
        for (int i = lane; i < DIN_; i += 32) s += gg[i] * RW[(size_t)j * DIN_ + i];
        #pragma unroll
        for (int o = 16; o; o >>= 1) s += __shfl_xor_sync(0xFFFFFFFFu, s, o);
        if (lane == 0) {
            float v = s + RB[j];
            tt[j] = 0.5f * v * (1.f + erff(v * 0.70710678118f));
        }
    }
    __syncthreads();
    float s = SB[d];
    #pragma unroll
    for (int j = 0; j < RED_; j++) s += tt[j] * SW[(size_t)d * RED_ + j];
    g_catt[z * DIN_ + d] = 1.f / (1.f + __expf(-s));
}

// ---------------- out = (sum_k y_k * catt_k) @ out_proj.T + bias ----------------
// tile 64M x 192N (full N), float4-over-K; g_y read exactly once
__global__ __launch_bounds__(256) void k_out(const float* __restrict__ W,
                                             const float* __restrict__ BI,
                                             float* __restrict__ OUT) {
    __shared__ float4 As[64][9];
    __shared__ float4 Ws[192][9];
    int m0 = blockIdx.x * 64;
    int b = m0 / L_;
    int l0 = m0 - b * L_;
    int tid = threadIdx.x;
    int tx = tid & 15, ty = tid >> 4;
    const float4* Y4 = (const float4*)g_y;
    const float4* C4 = (const float4*)g_catt;
    const float4* W4 = (const float4*)W;
    float acc[4][12] = {};
    for (int k0 = 0; k0 < 96; k0 += 8) {
        __syncthreads();
        #pragma unroll
        for (int i = 0; i < 2; i++) {
            int idx = tid + i * 256;
            int r = idx >> 3, kq = idx & 7;
            float4 s = {0.f, 0.f, 0.f, 0.f};
            #pragma unroll
            for (int dir = 0; dir < KDIR_; dir++) {
                float4 y4 = Y4[((size_t)(dir * B_ + b) * L_ + l0 + r) * 96 + k0 + kq];
                float4 c4 = C4[(size_t)(dir * B_ + b) * 96 + k0 + kq];
                s.x += y4.x * c4.x; s.y += y4.y * c4.y;
                s.z += y4.z * c4.z; s.w += y4.w * c4.w;
            }
            As[r][kq] = s;
        }
        #pragma unroll
        for (int i = 0; i < 6; i++) {
            int idx = tid + i * 256;
            int r = idx >> 3, kq = idx & 7;
            Ws[r][kq] = W4[(size_t)r * 96 + k0 + kq];
        }
        __syncthreads();
        #pragma unroll
        for (int kq = 0; kq < 8; kq++) {
            float4 a4[4], w4[12];
            #pragma unroll
            for (int i = 0; i < 4; i++) a4[i] = As[ty * 4 + i][kq];
            #pragma unroll
            for (int j = 0; j < 12; j++) w4[j] = Ws[tx + 16 * j][kq];
            #pragma unroll
            for (int i = 0; i < 4; i++)
                #pragma unroll
                for (int j = 0; j < 12; j++)
                    acc[i][j] += a4[i].x * w4[j].x + a4[i].y * w4[j].y +
                                 a4[i].z * w4[j].z + a4[i].w * w4[j].w;
        }
    }
    #pragma unroll
    for (int i = 0; i < 4; i++)
        #pragma unroll
        for (int j = 0; j < 12; j++)
            OUT[(size_t)(m0 + ty * 4 + i) * DM_ + tx + 16 * j] = acc[i][j] + BI[tx + 16 * j];
}

// ---------------- launch ----------------
extern "C" void kernel_launch(void* const* d_in, const int* in_sizes, int n_in,
                              void* d_out, int out_size) {
    const float* x          = (const float*)d_in[0];
    const float* in_proj_w  = (const float*)d_in[1];
    const float* conv_w     = (const float*)d_in[2];
    const float* conv_b     = (const float*)d_in[3];
    const float* x_proj_w   = (const float*)d_in[4];
    const float* dt_w       = (const float*)d_in[5];
    const float* dt_b       = (const float*)d_in[6];
    const float* A_log      = (const float*)d_in[7];
    const float* D_skip     = (const float*)d_in[8];
    const float* out_proj_w = (const float*)d_in[9];
    const float* out_proj_b = (const float*)d_in[10];
    const float* ln_g       = (const float*)d_in[11];
    const float* ln_b       = (const float*)d_in[12];
    const float* red_w      = (const float*)d_in[13];
    const float* red_b      = (const float*)d_in[14];
    const float* sel_w      = (const float*)d_in[15];
    const float* sel_b      = (const float*)d_in[16];
    const float* mask_w     = (const float*)d_in[17];
    const float* mask_b     = (const float*)d_in[18];
    float* out = (float*)d_out;

    k_mask<<<dim3((B_ * L_ + 7) / 8), dim3(32, 8)>>>(x, mask_w, mask_b);
    k_xz<<<dim3(12, 98), 256>>>(x, in_proj_w);
    k_conv<<<dim3(L_ / 32, 3, KDIR_ * B_), 128>>>(conv_w, conv_b);
    k_xdbl<<<dim3(25, KDIR_ * B_), 128>>>(x_proj_w);
    k_zero<<<24, 256>>>();
    k_scan1<<<dim3(NCH_, 3, KDIR_ * B_), 128>>>(A_log, dt_w, dt_b);
    k_fix<<<KDIR_ * B_, DIN_>>>(A_log);
    k_scan2<<<dim3(NCH_, 3, KDIR_ * B_), 128>>>(A_log, dt_w, dt_b, D_skip);
    k_lnstats<<<dim3(16, B_, KDIR_), 384>>>(ln_g, ln_b);
    k_attn<<<KDIR_ * B_, DIN_>>>(red_w, red_b, sel_w, sel_b);
    k_out<<<dim3(196), 256>>>(out_proj_w, out_proj_b, out);
}